// round 2
// baseline (speedup 1.0000x reference)
#include <cuda_runtime.h>

// Problem constants (fixed by the reference).
constexpr int NN = 100000;   // nodes
constexpr int NE = 1600000;  // edges
constexpr int F1 = 64;       // layer-1 out features (== Fin)
constexpr int F2 = 32;       // layer-2 out features

// Scratch (device globals — no runtime allocation allowed).
__device__ float g_dinv[NN];                 // deg accumulator, then rsqrt(deg+2)
__device__ int   g_src[NE];
__device__ int   g_dst[NE];
__device__ float g_hs1[(size_t)NN * F1];     // (x@W1) * dinv[row]
__device__ float g_acc1[(size_t)NN * F1];    // sum_{src->dst} hs1[src]
__device__ float g_hs2[(size_t)NN * F2];
__device__ float g_acc2[(size_t)NN * F2];
__device__ int   g_is64;

// ---------------------------------------------------------------------------
// Detect whether edge_index arrived as int64 or int32 (jax x64 flag dependent).
// For int64 little-endian with values < 2^31, every odd 32-bit word is 0.
// For int32, odd words are random node ids in [0,100000) — ~never all zero
// over 1024 samples. Deterministic for fixed input.
__global__ void detect_dtype(const unsigned int* __restrict__ w) {
    __shared__ int cnt;
    if (threadIdx.x == 0) cnt = 0;
    __syncthreads();
    if (w[threadIdx.x * 2 + 1] != 0u) atomicAdd(&cnt, 1);
    __syncthreads();
    if (threadIdx.x == 0) g_is64 = (cnt == 0) ? 1 : 0;
}

// ---------------------------------------------------------------------------
// Zero accumulators + degree.
__global__ void zero_all() {
    int i = blockIdx.x * blockDim.x + threadIdx.x;
    const int n1 = NN * F1 / 4;
    const int n2 = NN * F2 / 4;
    const int n3 = NN / 4;
    float4 z = make_float4(0.f, 0.f, 0.f, 0.f);
    if (i < n1)                ((float4*)g_acc1)[i] = z;
    else if (i < n1 + n2)      ((float4*)g_acc2)[i - n1] = z;
    else if (i < n1 + n2 + n3) ((float4*)g_dinv)[i - n1 - n2] = z;
}

// ---------------------------------------------------------------------------
// Convert indices to int32 + build degree histogram (float, via RED).
__global__ void prep_edges(const int* __restrict__ w) {
    int e = blockIdx.x * blockDim.x + threadIdx.x;
    if (e >= NE) return;
    int s, d;
    if (g_is64) {
        s = w[2 * e];               // low word of int64
        d = w[2 * (NE + e)];
    } else {
        s = w[e];
        d = w[NE + e];
    }
    g_src[e] = s;
    g_dst[e] = d;
    atomicAdd(&g_dinv[d], 1.0f);
}

__global__ void finish_dinv() {
    int i = blockIdx.x * blockDim.x + threadIdx.x;
    if (i < NN) g_dinv[i] = rsqrtf(g_dinv[i] + 2.0f);  // improved self-loops: +2
}

// ---------------------------------------------------------------------------
// GEMM: out[row, :] = (x[row, :] @ W) * dinv[row].  K = 64 fixed.
// 32 rows/block, 4x4 register micro-tile per thread.
template <int FOUT>
__global__ void gemm_scale(const float* __restrict__ x, const float* __restrict__ W) {
    constexpr int K = 64, ROWS = 32, XP = K + 4;  // padded smem stride (68)
    constexpr int TJ = FOUT / 4;
    constexpr int NT = (ROWS / 4) * TJ;           // 128 (F=64) / 64 (F=32) threads
    __shared__ float xs[ROWS][XP];
    __shared__ float ws[K][FOUT];
    float* out = (FOUT == 64) ? g_hs1 : g_hs2;

    int tid = threadIdx.x;
    int row0 = blockIdx.x * ROWS;

    // Stage x tile [32 x 64], vectorized, conflict-light.
    for (int f4 = tid; f4 < ROWS * K / 4; f4 += NT) {
        int r = f4 >> 4, kc = f4 & 15;
        float4 v = ((const float4*)(x + (size_t)(row0 + r) * K))[kc];
        *(float4*)&xs[r][kc * 4] = v;
    }
    // Stage W [64 x FOUT].
    for (int f4 = tid; f4 < K * FOUT / 4; f4 += NT)
        ((float4*)ws)[f4] = ((const float4*)W)[f4];
    __syncthreads();

    int j = tid % TJ;   // col group
    int i = tid / TJ;   // row group (0..7)
    float acc[4][4] = {};
#pragma unroll 8
    for (int k = 0; k < K; k++) {
        float av[4];
#pragma unroll
        for (int r = 0; r < 4; r++) av[r] = xs[i * 4 + r][k];
        float4 b = *(const float4*)&ws[k][j * 4];
#pragma unroll
        for (int r = 0; r < 4; r++) {
            acc[r][0] = fmaf(av[r], b.x, acc[r][0]);
            acc[r][1] = fmaf(av[r], b.y, acc[r][1]);
            acc[r][2] = fmaf(av[r], b.z, acc[r][2]);
            acc[r][3] = fmaf(av[r], b.w, acc[r][3]);
        }
    }
#pragma unroll
    for (int r = 0; r < 4; r++) {
        int row = row0 + i * 4 + r;
        float dv = g_dinv[row];
        float4 o = make_float4(acc[r][0] * dv, acc[r][1] * dv,
                               acc[r][2] * dv, acc[r][3] * dv);
        *(float4*)&out[(size_t)row * FOUT + j * 4] = o;
    }
}

// ---------------------------------------------------------------------------
// Edge scatter: acc[dst, :] += hs[src, :], vector float4 reductions.
// One thread per (edge, 4-float chunk).
template <int F>
__global__ void scatter_add() {
    constexpr int C = F / 4;
    const float* hs = (F == 64) ? g_hs1 : g_hs2;
    float* acc = (F == 64) ? g_acc1 : g_acc2;
    unsigned t = blockIdx.x * blockDim.x + threadIdx.x;
    if (t >= (unsigned)NE * C) return;
    int e = t / C;
    int c = t % C;
    int s = g_src[e];
    int d = g_dst[e];
    float4 v = ((const float4*)(hs + (size_t)s * F))[c];
    float* p = acc + (size_t)d * F + (size_t)c * 4;
    asm volatile("red.global.add.v4.f32 [%0], {%1, %2, %3, %4};"
                 :: "l"(p), "f"(v.x), "f"(v.y), "f"(v.z), "f"(v.w)
                 : "memory");
}

// ---------------------------------------------------------------------------
// Layer-1 epilogue: h1 = relu(dinv*(acc1 + 2*hs1) + b1)  -> feature_map.
__global__ void epilogue1(const float* __restrict__ b, float* __restrict__ feat) {
    int i = blockIdx.x * blockDim.x + threadIdx.x;
    if (i >= NN * (F1 / 4)) return;
    int row = i >> 4;
    float dv = g_dinv[row];
    float4 a = ((const float4*)g_acc1)[i];
    float4 h = ((const float4*)g_hs1)[i];
    float4 bb = ((const float4*)b)[i & 15];
    float4 o;
    o.x = fmaxf(fmaf(dv, fmaf(2.f, h.x, a.x), bb.x), 0.f);
    o.y = fmaxf(fmaf(dv, fmaf(2.f, h.y, a.y), bb.y), 0.f);
    o.z = fmaxf(fmaf(dv, fmaf(2.f, h.z, a.z), bb.z), 0.f);
    o.w = fmaxf(fmaf(dv, fmaf(2.f, h.w, a.w), bb.w), 0.f);
    ((float4*)feat)[i] = o;
}

// Layer-2 epilogue: out = dinv*(acc2 + 2*hs2) + b2 (no relu).
__global__ void epilogue2(const float* __restrict__ b, float* __restrict__ out) {
    int i = blockIdx.x * blockDim.x + threadIdx.x;
    if (i >= NN * (F2 / 4)) return;
    int row = i >> 3;
    float dv = g_dinv[row];
    float4 a = ((const float4*)g_acc2)[i];
    float4 h = ((const float4*)g_hs2)[i];
    float4 bb = ((const float4*)b)[i & 7];
    float4 o;
    o.x = fmaf(dv, fmaf(2.f, h.x, a.x), bb.x);
    o.y = fmaf(dv, fmaf(2.f, h.y, a.y), bb.y);
    o.z = fmaf(dv, fmaf(2.f, h.z, a.z), bb.z);
    o.w = fmaf(dv, fmaf(2.f, h.w, a.w), bb.w);
    ((float4*)out)[i] = o;
}

// ---------------------------------------------------------------------------
extern "C" void kernel_launch(void* const* d_in, const int* in_sizes, int n_in,
                              void* d_out, int out_size) {
    const float* x  = (const float*)d_in[0];
    const int*   ei = (const int*)d_in[1];   // int32 view; dtype auto-detected
    const float* W1 = (const float*)d_in[2];
    const float* b1 = (const float*)d_in[3];
    const float* W2 = (const float*)d_in[4];
    const float* b2 = (const float*)d_in[5];

    float* out  = (float*)d_out;                      // [N, 32]
    float* feat = out + (size_t)NN * F2;              // [N, 64] feature_map

    detect_dtype<<<1, 1024>>>((const unsigned int*)ei);

    int zt = NN * F1 / 4 + NN * F2 / 4 + NN / 4;
    zero_all<<<(zt + 255) / 256, 256>>>();

    prep_edges<<<(NE + 255) / 256, 256>>>(ei);
    finish_dinv<<<(NN + 255) / 256, 256>>>();

    // Layer 1
    gemm_scale<F1><<<NN / 32, 128>>>(x, W1);
    scatter_add<F1><<<(NE * (F1 / 4) + 255) / 256, 256>>>();
    epilogue1<<<(NN * (F1 / 4) + 255) / 256, 256>>>(b1, feat);

    // Layer 2 (reads h1 from the feature_map output region)
    gemm_scale<F2><<<NN / 32, 64>>>(feat, W2);
    scatter_add<F2><<<(NE * (F2 / 4) + 255) / 256, 256>>>();
    epilogue2<<<(NN * (F2 / 4) + 255) / 256, 256>>>(b2, out);
}

// round 3
// speedup vs baseline: 1.3412x; 1.3412x over previous
#include <cuda_runtime.h>

// Problem constants (fixed by the reference).
constexpr int NN = 100000;   // nodes
constexpr int NE = 1600000;  // edges
constexpr int F1 = 64;       // layer-1 out features (== Fin)
constexpr int F2 = 32;       // layer-2 out features
constexpr int NB = (NN + 255) / 256;  // 391 scan blocks

// Scratch (device globals — no runtime allocation allowed).
__device__ int   g_deg[NN];
__device__ int   g_off[NN + 1];
__device__ int   g_cur[NN];
__device__ int   g_bsum[NB];
__device__ int   g_src[NE];
__device__ int   g_dst[NE];
__device__ int   g_csr_src[NE];
__device__ float g_dinv[NN];
__device__ float g_hs1[(size_t)NN * F1];   // (x@W1) * dinv[row]
__device__ float g_hs2[(size_t)NN * F2];   // (h1@W2) * dinv[row]
__device__ int   g_is64;

// ---------------------------------------------------------------------------
// Detect int64 vs int32 edge_index (jax x64-flag dependent). For int64 LE with
// values < 2^31 all odd 32-bit words are zero; for int32 they are random ids.
__global__ void detect_dtype(const unsigned int* __restrict__ w) {
    __shared__ int cnt;
    if (threadIdx.x == 0) cnt = 0;
    __syncthreads();
    if (w[threadIdx.x * 2 + 1] != 0u) atomicAdd(&cnt, 1);
    __syncthreads();
    if (threadIdx.x == 0) g_is64 = (cnt == 0) ? 1 : 0;
}

__global__ void zero_deg() {
    int i = blockIdx.x * blockDim.x + threadIdx.x;
    if (i < NN) g_deg[i] = 0;
}

// Convert indices to int32 + integer degree histogram.
__global__ void prep_edges(const int* __restrict__ w) {
    int e = blockIdx.x * blockDim.x + threadIdx.x;
    if (e >= NE) return;
    int s, d;
    if (g_is64) {
        s = w[2 * e];
        d = w[2 * (NE + e)];
    } else {
        s = w[e];
        d = w[NE + e];
    }
    g_src[e] = s;
    g_dst[e] = d;
    atomicAdd(&g_deg[d], 1);
}

__global__ void finish_dinv() {
    int i = blockIdx.x * blockDim.x + threadIdx.x;
    if (i < NN) g_dinv[i] = rsqrtf((float)g_deg[i] + 2.0f);  // improved: +2
}

// ---------------------------------------------------------------------------
// 3-kernel exclusive scan of g_deg -> g_off (and g_cur copy).
__global__ void block_sum() {
    int i = blockIdx.x * 256 + threadIdx.x;
    int v = (i < NN) ? g_deg[i] : 0;
    int lane = threadIdx.x & 31, wid = threadIdx.x >> 5;
#pragma unroll
    for (int o = 16; o > 0; o >>= 1) v += __shfl_down_sync(0xffffffffu, v, o);
    __shared__ int ws[8];
    if (lane == 0) ws[wid] = v;
    __syncthreads();
    if (threadIdx.x == 0) {
        int s = 0;
#pragma unroll
        for (int k = 0; k < 8; k++) s += ws[k];
        g_bsum[blockIdx.x] = s;
    }
}

__global__ void scan_bsum() {  // 1 block, 512 threads, NB=391 entries
    __shared__ int s[512];
    int t = threadIdx.x;
    int orig = (t < NB) ? g_bsum[t] : 0;
    s[t] = orig;
    __syncthreads();
#pragma unroll
    for (int o = 1; o < 512; o <<= 1) {
        int v = (t >= o) ? s[t - o] : 0;
        __syncthreads();
        s[t] += v;
        __syncthreads();
    }
    if (t < NB) g_bsum[t] = s[t] - orig;  // exclusive
}

__global__ void scan_final() {
    int i = blockIdx.x * 256 + threadIdx.x;
    int v = (i < NN) ? g_deg[i] : 0;
    int lane = threadIdx.x & 31, wid = threadIdx.x >> 5;
    int x = v;
#pragma unroll
    for (int o = 1; o < 32; o <<= 1) {
        int y = __shfl_up_sync(0xffffffffu, x, o);
        if (lane >= o) x += y;
    }
    __shared__ int ws[8];
    if (lane == 31) ws[wid] = x;
    __syncthreads();
    if (threadIdx.x == 0) {
        int r = 0;
#pragma unroll
        for (int k = 0; k < 8; k++) { int t = ws[k]; ws[k] = r; r += t; }
    }
    __syncthreads();
    int off = g_bsum[blockIdx.x] + ws[wid] + (x - v);  // exclusive
    if (i < NN) {
        g_off[i] = off;
        g_cur[i] = off;
        if (i == NN - 1) g_off[NN] = off + v;
    }
}

__global__ void fill_csr() {
    int e = blockIdx.x * blockDim.x + threadIdx.x;
    if (e >= NE) return;
    int pos = atomicAdd(&g_cur[g_dst[e]], 1);
    g_csr_src[pos] = g_src[e];
}

// ---------------------------------------------------------------------------
// GEMM: out[row, :] = (x[row, :] @ W) * dinv[row].  K = 64 fixed.
template <int FOUT>
__global__ void gemm_scale(const float* __restrict__ x, const float* __restrict__ W) {
    constexpr int K = 64, ROWS = 32, XP = K + 4;
    constexpr int TJ = FOUT / 4;
    constexpr int NT = (ROWS / 4) * TJ;
    __shared__ float xs[ROWS][XP];
    __shared__ float ws[K][FOUT];
    float* out = (FOUT == 64) ? g_hs1 : g_hs2;

    int tid = threadIdx.x;
    int row0 = blockIdx.x * ROWS;

    for (int f4 = tid; f4 < ROWS * K / 4; f4 += NT) {
        int r = f4 >> 4, kc = f4 & 15;
        float4 v = ((const float4*)(x + (size_t)(row0 + r) * K))[kc];
        *(float4*)&xs[r][kc * 4] = v;
    }
    for (int f4 = tid; f4 < K * FOUT / 4; f4 += NT)
        ((float4*)ws)[f4] = ((const float4*)W)[f4];
    __syncthreads();

    int j = tid % TJ;
    int i = tid / TJ;
    float acc[4][4] = {};
#pragma unroll 8
    for (int k = 0; k < K; k++) {
        float av[4];
#pragma unroll
        for (int r = 0; r < 4; r++) av[r] = xs[i * 4 + r][k];
        float4 b = *(const float4*)&ws[k][j * 4];
#pragma unroll
        for (int r = 0; r < 4; r++) {
            acc[r][0] = fmaf(av[r], b.x, acc[r][0]);
            acc[r][1] = fmaf(av[r], b.y, acc[r][1]);
            acc[r][2] = fmaf(av[r], b.z, acc[r][2]);
            acc[r][3] = fmaf(av[r], b.w, acc[r][3]);
        }
    }
#pragma unroll
    for (int r = 0; r < 4; r++) {
        int row = row0 + i * 4 + r;
        float dv = g_dinv[row];
        float4 o = make_float4(acc[r][0] * dv, acc[r][1] * dv,
                               acc[r][2] * dv, acc[r][3] * dv);
        *(float4*)&out[(size_t)row * FOUT + j * 4] = o;
    }
}

// ---------------------------------------------------------------------------
// Pull aggregation, one warp per dst node, fused epilogue.
// F=64: each lane owns a float2 slice of the row.
__global__ void agg1(const float* __restrict__ b, float* __restrict__ feat) {
    int warp = (blockIdx.x * 256 + threadIdx.x) >> 5;
    int lane = threadIdx.x & 31;
    if (warp >= NN) return;
    int beg = g_off[warp], end = g_off[warp + 1];
    const float2* hs = (const float2*)g_hs1;
    float ax = 0.f, ay = 0.f;
    int i = beg;
    for (; i + 4 <= end; i += 4) {
        int s0 = g_csr_src[i], s1 = g_csr_src[i + 1];
        int s2 = g_csr_src[i + 2], s3 = g_csr_src[i + 3];
        float2 v0 = hs[s0 * 32 + lane];
        float2 v1 = hs[s1 * 32 + lane];
        float2 v2 = hs[s2 * 32 + lane];
        float2 v3 = hs[s3 * 32 + lane];
        ax += (v0.x + v1.x) + (v2.x + v3.x);
        ay += (v0.y + v1.y) + (v2.y + v3.y);
    }
    for (; i < end; i++) {
        float2 v = hs[g_csr_src[i] * 32 + lane];
        ax += v.x;
        ay += v.y;
    }
    float dv = g_dinv[warp];
    float2 h = hs[warp * 32 + lane];
    float2 bb = ((const float2*)b)[lane];
    float2 o;
    o.x = fmaxf(fmaf(dv, fmaf(2.f, h.x, ax), bb.x), 0.f);
    o.y = fmaxf(fmaf(dv, fmaf(2.f, h.y, ay), bb.y), 0.f);
    ((float2*)feat)[warp * 32 + lane] = o;
}

// F=32: each lane owns one float of the row.
__global__ void agg2(const float* __restrict__ b, float* __restrict__ out) {
    int warp = (blockIdx.x * 256 + threadIdx.x) >> 5;
    int lane = threadIdx.x & 31;
    if (warp >= NN) return;
    int beg = g_off[warp], end = g_off[warp + 1];
    const float* hs = g_hs2;
    float a = 0.f;
    int i = beg;
    for (; i + 4 <= end; i += 4) {
        int s0 = g_csr_src[i], s1 = g_csr_src[i + 1];
        int s2 = g_csr_src[i + 2], s3 = g_csr_src[i + 3];
        float v0 = hs[s0 * 32 + lane];
        float v1 = hs[s1 * 32 + lane];
        float v2 = hs[s2 * 32 + lane];
        float v3 = hs[s3 * 32 + lane];
        a += (v0 + v1) + (v2 + v3);
    }
    for (; i < end; i++) a += hs[g_csr_src[i] * 32 + lane];
    float dv = g_dinv[warp];
    float h = hs[warp * 32 + lane];
    out[warp * 32 + lane] = fmaf(dv, fmaf(2.f, h, a), b[lane]);
}

// ---------------------------------------------------------------------------
extern "C" void kernel_launch(void* const* d_in, const int* in_sizes, int n_in,
                              void* d_out, int out_size) {
    const float* x  = (const float*)d_in[0];
    const int*   ei = (const int*)d_in[1];
    const float* W1 = (const float*)d_in[2];
    const float* b1 = (const float*)d_in[3];
    const float* W2 = (const float*)d_in[4];
    const float* b2 = (const float*)d_in[5];

    float* out  = (float*)d_out;              // [N, 32]
    float* feat = out + (size_t)NN * F2;      // [N, 64] feature_map

    detect_dtype<<<1, 1024>>>((const unsigned int*)ei);
    zero_deg<<<NB, 256>>>();
    prep_edges<<<(NE + 255) / 256, 256>>>(ei);

    // CSR build
    block_sum<<<NB, 256>>>();
    scan_bsum<<<1, 512>>>();
    scan_final<<<NB, 256>>>();
    fill_csr<<<(NE + 255) / 256, 256>>>();
    finish_dinv<<<NB, 256>>>();

    // Layer 1
    gemm_scale<F1><<<NN / 32, 128>>>(x, W1);
    agg1<<<(NN * 32 + 255) / 256, 256>>>(b1, feat);

    // Layer 2 (reads h1 from the feature_map output region)
    gemm_scale<F2><<<NN / 32, 64>>>(feat, W2);
    agg2<<<(NN * 32 + 255) / 256, 256>>>(b2, out);
}